// round 1
// baseline (speedup 1.0000x reference)
#include <cuda_runtime.h>
#include <cuda_bf16.h>
#include <math.h>

// Problem dims (fixed by the dataset): x [2,2048,2048] -> tokens T=4096, H=2048, I=8192
#define T_TOK 4096
#define HDIM  2048
#define IDIM  8192
#define NGATE 16384   // 2*I rows in w_gate

// ---------------- device scratch (static, allocation-free) ----------------
__device__ double      d_abssum[2];
__device__ float       d_wscale[2];   // s = 1/clip(mean|w|,1e-5)
__device__ float       d_winv[2];     // 1/s  (dequant factor)
__device__ signed char d_wqg[(long long)NGATE * HDIM];   // ternary gate/up weights
__device__ signed char d_wqd[(long long)HDIM * IDIM];    // ternary down weights
__device__ signed char d_xq[(long long)T_TOK * HDIM];    // quantized activations (layer 1)
__device__ float       d_as1[T_TOK];                     // per-token dequant (layer 1)
__device__ float       d_h[(long long)T_TOK * IDIM];     // SwiGLU output (fp32)
__device__ signed char d_hq[(long long)T_TOK * IDIM];    // quantized activations (layer 2)
__device__ float       d_as2[T_TOK];                     // per-token dequant (layer 2)

// ---------------- small utility kernels ----------------
__global__ void k_zero() { d_abssum[0] = 0.0; d_abssum[1] = 0.0; }

__global__ void k_abssum(const float* __restrict__ w, long long n, int slot) {
    float s = 0.f;
    long long stride = (long long)gridDim.x * blockDim.x;
    for (long long i = (long long)blockIdx.x * blockDim.x + threadIdx.x; i < n; i += stride)
        s += fabsf(w[i]);
    #pragma unroll
    for (int o = 16; o > 0; o >>= 1) s += __shfl_xor_sync(0xffffffffu, s, o);
    __shared__ double sb[8];
    int wid = threadIdx.x >> 5, lane = threadIdx.x & 31;
    if (lane == 0) sb[wid] = (double)s;
    __syncthreads();
    if (threadIdx.x == 0) {
        double t = 0.0;
        #pragma unroll
        for (int i = 0; i < 8; i++) t += sb[i];
        atomicAdd(&d_abssum[slot], t);
    }
}

__global__ void k_wscale() {
    float m0 = (float)(d_abssum[0] / (double)((long long)NGATE * HDIM));
    float m1 = (float)(d_abssum[1] / (double)((long long)HDIM * IDIM));
    float s0 = 1.f / fmaxf(m0, 1e-5f);
    float s1 = 1.f / fmaxf(m1, 1e-5f);
    d_wscale[0] = s0; d_wscale[1] = s1;
    d_winv[0] = 1.f / s0; d_winv[1] = 1.f / s1;
}

// ternarize: clip(round(w*s), -1, 1) stored as int8
__global__ void k_wquant(const float4* __restrict__ w, long long n4, int which) {
    float s = d_wscale[which];
    signed char* q = which ? d_wqd : d_wqg;
    char4* q4 = reinterpret_cast<char4*>(q);
    long long stride = (long long)gridDim.x * blockDim.x;
    for (long long i = (long long)blockIdx.x * blockDim.x + threadIdx.x; i < n4; i += stride) {
        float4 v = w[i];
        char4 c;
        c.x = (signed char)fminf(fmaxf(rintf(v.x * s), -1.f), 1.f);
        c.y = (signed char)fminf(fmaxf(rintf(v.y * s), -1.f), 1.f);
        c.z = (signed char)fminf(fmaxf(rintf(v.z * s), -1.f), 1.f);
        c.w = (signed char)fminf(fmaxf(rintf(v.w * s), -1.f), 1.f);
        q4[i] = c;
    }
}

// ---------------- block reduction helper ----------------
__device__ __forceinline__ float block_reduce(float v, bool isMax) {
    __shared__ float sb[8];
    __syncthreads();   // protect sb from any previous use
    #pragma unroll
    for (int o = 16; o > 0; o >>= 1) {
        float t = __shfl_xor_sync(0xffffffffu, v, o);
        v = isMax ? fmaxf(v, t) : (v + t);
    }
    int wid = threadIdx.x >> 5, lane = threadIdx.x & 31;
    if (lane == 0) sb[wid] = v;
    __syncthreads();
    float r;
    if (isMax) {
        r = fmaxf(fmaxf(fmaxf(sb[0], sb[1]), fmaxf(sb[2], sb[3])),
                  fmaxf(fmaxf(sb[4], sb[5]), fmaxf(sb[6], sb[7])));
    } else {
        r = sb[0] + sb[1] + sb[2] + sb[3] + sb[4] + sb[5] + sb[6] + sb[7];
    }
    return r;
}

// ---------------- RMSNorm + per-token int8 quantization ----------------
// one block (256 threads) per token; HID/256 values per thread held in registers
template <int HID, int VPT>
__global__ void __launch_bounds__(256) k_actquant(
    const float* __restrict__ x, const float* __restrict__ g,
    signed char* __restrict__ q, float* __restrict__ ascale)
{
    long long t = blockIdx.x;
    const float* xr = x + t * HID;
    float v[VPT];
    float ss = 0.f;
    #pragma unroll
    for (int j = 0; j < VPT; j++) {
        float f = xr[threadIdx.x + j * 256];
        v[j] = f;
        ss += f * f;
    }
    float var = block_reduce(ss, false) * (1.f / (float)HID);
    float r = rsqrtf(var + 1e-5f);
    float amax = 0.f;
    #pragma unroll
    for (int j = 0; j < VPT; j++) {
        float xn = v[j] * r * g[threadIdx.x + j * 256];
        v[j] = xn;
        amax = fmaxf(amax, fabsf(xn));
    }
    amax = block_reduce(amax, true);
    float s = 127.f / fmaxf(amax, 1e-5f);
    signed char* qr = q + t * HID;
    #pragma unroll
    for (int j = 0; j < VPT; j++) {
        float qf = fminf(fmaxf(rintf(v[j] * s), -128.f), 127.f);
        qr[threadIdx.x + j * 256] = (signed char)qf;
    }
    if (threadIdx.x == 0) ascale[t] = 1.f / s;
}

// ---------------- GEMM1 (x_q @ w_gate^T) fused with SwiGLU ----------------
// C tile: BM=128 x BN=64 for BOTH the gate half (rows n) and v half (rows n+I).
// A = d_xq [T,H] int8, B = d_wqg [2I,H] int8 ternary. K = 2048 bytes.
// smem layout transposed [k-chunk][row] so compute-side LDS are conflict-free.
__global__ void __launch_bounds__(256) k_gemm1_swiglu() {
    const int* __restrict__ Aq = reinterpret_cast<const int*>(d_xq);
    const int* __restrict__ Wg = reinterpret_cast<const int*>(d_wqg);
    __shared__ int As[16][128];
    __shared__ int Bgs[16][64];
    __shared__ int Bvs[16][64];

    const int mBase = blockIdx.y * 128;
    const int nBase = blockIdx.x * 64;
    const int tid = threadIdx.x;
    const int tx = tid & 15;        // 16 cols of threads -> n
    const int ty = tid >> 4;        // 16 rows of threads -> m
    const int KI = HDIM / 4;        // 512 ints per row

    int accg[8][4] = {};
    int accv[8][4] = {};

    for (int kt = 0; kt < HDIM / 64; kt++) {
        int k0 = kt * 16;  // int offset into row
        // load A: 128 rows x 16 ints, 2 passes of 256 int4 loads
        #pragma unroll
        for (int rr = 0; rr < 2; rr++) {
            int u = tid + rr * 256;
            int m = u >> 2, c = u & 3;
            int4 val = *reinterpret_cast<const int4*>(Aq + (long long)(mBase + m) * KI + k0 + c * 4);
            As[c * 4 + 0][m] = val.x; As[c * 4 + 1][m] = val.y;
            As[c * 4 + 2][m] = val.z; As[c * 4 + 3][m] = val.w;
        }
        // load Bg / Bv: 64 rows x 16 ints each
        {
            int n = tid >> 2, c = tid & 3;
            int4 vg = *reinterpret_cast<const int4*>(Wg + (long long)(nBase + n) * KI + k0 + c * 4);
            Bgs[c * 4 + 0][n] = vg.x; Bgs[c * 4 + 1][n] = vg.y;
            Bgs[c * 4 + 2][n] = vg.z; Bgs[c * 4 + 3][n] = vg.w;
            int4 vv = *reinterpret_cast<const int4*>(Wg + (long long)(nBase + IDIM + n) * KI + k0 + c * 4);
            Bvs[c * 4 + 0][n] = vv.x; Bvs[c * 4 + 1][n] = vv.y;
            Bvs[c * 4 + 2][n] = vv.z; Bvs[c * 4 + 3][n] = vv.w;
        }
        __syncthreads();
        #pragma unroll
        for (int kk = 0; kk < 16; kk++) {
            const int4 a0 = *reinterpret_cast<const int4*>(&As[kk][ty * 8]);
            const int4 a1 = *reinterpret_cast<const int4*>(&As[kk][ty * 8 + 4]);
            const int4 bg4 = *reinterpret_cast<const int4*>(&Bgs[kk][tx * 4]);
            const int4 bv4 = *reinterpret_cast<const int4*>(&Bvs[kk][tx * 4]);
            int a[8] = {a0.x, a0.y, a0.z, a0.w, a1.x, a1.y, a1.z, a1.w};
            int bg[4] = {bg4.x, bg4.y, bg4.z, bg4.w};
            int bv[4] = {bv4.x, bv4.y, bv4.z, bv4.w};
            #pragma unroll
            for (int i = 0; i < 8; i++) {
                #pragma unroll
                for (int j = 0; j < 4; j++) {
                    accg[i][j] = __dp4a(a[i], bg[j], accg[i][j]);
                    accv[i][j] = __dp4a(a[i], bv[j], accv[i][j]);
                }
            }
        }
        __syncthreads();
    }

    const float wig = d_winv[0];
    #pragma unroll
    for (int i = 0; i < 8; i++) {
        int m = mBase + ty * 8 + i;
        float sc = d_as1[m] * wig;
        float4 o;
        float* op = &o.x;
        #pragma unroll
        for (int j = 0; j < 4; j++) {
            float gv = (float)accg[i][j] * sc;
            float vv = (float)accv[i][j] * sc;
            // silu(gate) * v
            op[j] = gv / (1.f + expf(-gv)) * vv;
        }
        *reinterpret_cast<float4*>(&d_h[(long long)m * IDIM + nBase + tx * 4]) = o;
    }
}

// ---------------- GEMM2 (h_q @ w_down^T) -> fp32 out ----------------
__global__ void __launch_bounds__(256) k_gemm2(float* __restrict__ out) {
    const int* __restrict__ Aq = reinterpret_cast<const int*>(d_hq);
    const int* __restrict__ W  = reinterpret_cast<const int*>(d_wqd);
    __shared__ int As[16][128];
    __shared__ int Bs[16][64];

    const int mBase = blockIdx.y * 128;
    const int nBase = blockIdx.x * 64;
    const int tid = threadIdx.x;
    const int tx = tid & 15;
    const int ty = tid >> 4;
    const int KI = IDIM / 4;   // 2048 ints per row

    int acc[8][4] = {};

    for (int kt = 0; kt < IDIM / 64; kt++) {
        int k0 = kt * 16;
        #pragma unroll
        for (int rr = 0; rr < 2; rr++) {
            int u = tid + rr * 256;
            int m = u >> 2, c = u & 3;
            int4 val = *reinterpret_cast<const int4*>(Aq + (long long)(mBase + m) * KI + k0 + c * 4);
            As[c * 4 + 0][m] = val.x; As[c * 4 + 1][m] = val.y;
            As[c * 4 + 2][m] = val.z; As[c * 4 + 3][m] = val.w;
        }
        {
            int n = tid >> 2, c = tid & 3;
            int4 vb = *reinterpret_cast<const int4*>(W + (long long)(nBase + n) * KI + k0 + c * 4);
            Bs[c * 4 + 0][n] = vb.x; Bs[c * 4 + 1][n] = vb.y;
            Bs[c * 4 + 2][n] = vb.z; Bs[c * 4 + 3][n] = vb.w;
        }
        __syncthreads();
        #pragma unroll
        for (int kk = 0; kk < 16; kk++) {
            const int4 a0 = *reinterpret_cast<const int4*>(&As[kk][ty * 8]);
            const int4 a1 = *reinterpret_cast<const int4*>(&As[kk][ty * 8 + 4]);
            const int4 b4 = *reinterpret_cast<const int4*>(&Bs[kk][tx * 4]);
            int a[8] = {a0.x, a0.y, a0.z, a0.w, a1.x, a1.y, a1.z, a1.w};
            int b[4] = {b4.x, b4.y, b4.z, b4.w};
            #pragma unroll
            for (int i = 0; i < 8; i++) {
                #pragma unroll
                for (int j = 0; j < 4; j++)
                    acc[i][j] = __dp4a(a[i], b[j], acc[i][j]);
            }
        }
        __syncthreads();
    }

    const float wid = d_winv[1];
    #pragma unroll
    for (int i = 0; i < 8; i++) {
        int m = mBase + ty * 8 + i;
        float sc = d_as2[m] * wid;
        float4 o;
        o.x = (float)acc[i][0] * sc;
        o.y = (float)acc[i][1] * sc;
        o.z = (float)acc[i][2] * sc;
        o.w = (float)acc[i][3] * sc;
        *reinterpret_cast<float4*>(&out[(long long)m * HDIM + nBase + tx * 4]) = o;
    }
}

// accessor kernels for __device__ buffers (pointers resolved device-side)
__global__ void k_actquant1_launcher(const float* x, const float* g) {
    // never launched; placeholder
}

extern "C" void kernel_launch(void* const* d_in, const int* in_sizes, int n_in,
                              void* d_out, int out_size) {
    const float* x      = (const float*)d_in[0];
    const float* w_gate = (const float*)d_in[1];
    const float* g_gate = (const float*)d_in[2];
    const float* w_down = (const float*)d_in[3];
    const float* g_down = (const float*)d_in[4];
    float* out = (float*)d_out;

    // device-symbol pointers (host-side resolution of __device__ arrays)
    signed char* p_xq = nullptr; float* p_as1 = nullptr;
    float* p_h = nullptr; signed char* p_hq = nullptr; float* p_as2 = nullptr;
    cudaGetSymbolAddress((void**)&p_xq,  d_xq);
    cudaGetSymbolAddress((void**)&p_as1, d_as1);
    cudaGetSymbolAddress((void**)&p_h,   d_h);
    cudaGetSymbolAddress((void**)&p_hq,  d_hq);
    cudaGetSymbolAddress((void**)&p_as2, d_as2);

    // 1) weight scale reductions
    k_zero<<<1, 1>>>();
    k_abssum<<<2048, 256>>>(w_gate, (long long)NGATE * HDIM, 0);
    k_abssum<<<1024, 256>>>(w_down, (long long)HDIM * IDIM, 1);
    k_wscale<<<1, 1>>>();

    // 2) ternarize weights
    k_wquant<<<4096, 256>>>((const float4*)w_gate, (long long)NGATE * HDIM / 4, 0);
    k_wquant<<<2048, 256>>>((const float4*)w_down, (long long)HDIM * IDIM / 4, 1);

    // 3) RMSNorm + quantize x
    k_actquant<HDIM, HDIM / 256><<<T_TOK, 256>>>(x, g_gate, p_xq, p_as1);

    // 4) GEMM1 + SwiGLU -> h
    k_gemm1_swiglu<<<dim3(IDIM / 64, T_TOK / 128), 256>>>();

    // 5) RMSNorm + quantize h
    k_actquant<IDIM, IDIM / 256><<<T_TOK, 256>>>(p_h, g_down, p_hq, p_as2);

    // 6) GEMM2 -> out
    k_gemm2<<<dim3(HDIM / 64, T_TOK / 128), 256>>>(out);
}